// round 6
// baseline (speedup 1.0000x reference)
#include <cuda_runtime.h>
#include <cstdint>

// Stacked LSTM (2 layers, D=H=6) + softmax, sm_103a.
// Warp-specialized: in each 128-thread block, warps 0-1 compute LAYER 0 for 10
// batch elements, warps 2-3 compute LAYER 1 for the same elements. h0 is handed
// off through a double-buffered shared-memory ring in CHUNK-step chunks with one
// __syncthreads() per chunk. Each warp's serial step is ONE LSTM cell (instead
// of two), halving the per-step static schedule that bounds this latency-
// dominated recurrence. Gate dots use packed fma.rn.f32x2 (gate pairs (i,f),
// (g,o)); sigmoid gates pre-halved so sigmoid = tanh.approx + FFMA.

#define FULLMASK 0xFFFFFFFFu
#define CHUNK 16
typedef unsigned long long ull;

__device__ __forceinline__ float ex2f(float x) {
    float r; asm("ex2.approx.f32 %0, %1;" : "=f"(r) : "f"(x)); return r;
}
__device__ __forceinline__ float rcpf(float x) {
    float r; asm("rcp.approx.f32 %0, %1;" : "=f"(r) : "f"(x)); return r;
}
__device__ __forceinline__ float htanh(float x) {
    float r; asm("tanh.approx.f32 %0, %1;" : "=f"(r) : "f"(x)); return r;
}
__device__ __forceinline__ ull pack2(float lo, float hi) {
    ull r; asm("mov.b64 %0, {%1, %2};" : "=l"(r) : "f"(lo), "f"(hi)); return r;
}
__device__ __forceinline__ ull dup2(float v) {
    ull r; asm("mov.b64 %0, {%1, %1};" : "=l"(r) : "f"(v)); return r;
}
__device__ __forceinline__ void unpack2(ull v, float& lo, float& hi) {
    asm("mov.b64 {%0, %1}, %2;" : "=f"(lo), "=f"(hi) : "l"(v));
}
__device__ __forceinline__ ull ffma2(ull a, ull b, ull c) {
    ull d; asm("fma.rn.f32x2 %0, %1, %2, %3;" : "=l"(d) : "l"(a), "l"(b), "l"(c)); return d;
}

// p01={a_i,a_f} (pre-halved), p23={a_g, a_o(pre-halved)}
__device__ __forceinline__ void gates_update(ull p01, ull p23, float& c, float& nh) {
    float a0, a1, a2, a3;
    unpack2(p01, a0, a1);
    unpack2(p23, a2, a3);
    float ig = fmaf(0.5f, htanh(a0), 0.5f);
    float fg = fmaf(0.5f, htanh(a1), 0.5f);
    float gg = htanh(a2);
    float og = fmaf(0.5f, htanh(a3), 0.5f);
    c  = fmaf(fg, c, ig * gg);
    nh = og * htanh(c);
}

__global__ __launch_bounds__(128, 1)
void stacked_lstm_kernel(const float* __restrict__ x,
                         const float* __restrict__ Wih0, const float* __restrict__ Whh0,
                         const float* __restrict__ bih0, const float* __restrict__ bhh0,
                         const float* __restrict__ Wih1, const float* __restrict__ Whh1,
                         const float* __restrict__ bih1, const float* __restrict__ bhh1,
                         float* __restrict__ out,
                         int B, int T) {
    const int tid  = threadIdx.x;
    const int w    = tid >> 5;
    const int lane = tid & 31;
    const int g    = lane / 6;            // group within warp (0..4 active)
    const int j    = lane - g * 6;        // hidden unit owned by this lane
    const int base = g * 6;
    const bool lactive  = (g < 5);
    const bool producer = (w < 2);        // warps 0,1: layer0; warps 2,3: layer1
    const int pe = w & 1;                 // which half of the block's 10 elems
    const int eb = pe * 5 + g;            // elem index within block (0..9)
    const int b  = blockIdx.x * 10 + eb;
    const bool valid = lactive && (b < B);
    const int bc = (b < B) ? b : (B - 1);

    // h0 handoff ring: [buf][step-in-chunk][elem][unit]
    __shared__ float h0buf[2][CHUNK][10][6];

    // ---- own-layer weights, packed gate pairs; i,f,o pre-halved ----
    const float* Wih = producer ? Wih0 : Wih1;
    const float* Whh = producer ? Whh0 : Whh1;
    const float* bih = producer ? bih0 : bih1;
    const float* bhh = producer ? bhh0 : bhh1;

    ull wip01[6], wip23[6], whp01[6], whp23[6], bzp01, bzp23;
    {
        const float s0 = 0.5f, s1 = 0.5f, s2 = 1.0f, s3 = 0.5f;  // i,f,g,o
        int r0 = j, r1 = 6 + j, r2 = 12 + j, r3 = 18 + j;
        bzp01 = pack2((bih[r0] + bhh[r0]) * s0, (bih[r1] + bhh[r1]) * s1);
        bzp23 = pack2((bih[r2] + bhh[r2]) * s2, (bih[r3] + bhh[r3]) * s3);
#pragma unroll
        for (int d = 0; d < 6; ++d) {
            wip01[d] = pack2(Wih[r0 * 6 + d] * s0, Wih[r1 * 6 + d] * s1);
            wip23[d] = pack2(Wih[r2 * 6 + d] * s2, Wih[r3 * 6 + d] * s3);
            whp01[d] = pack2(Whh[r0 * 6 + d] * s0, Whh[r1 * 6 + d] * s1);
            whp23[d] = pack2(Whh[r2 * 6 + d] * s2, Whh[r3 * 6 + d] * s3);
        }
    }

    // ---- recurrent state (own layer) ----
    float cst = 0.0f;
    ull hp[6];
    float h1f[6];
#pragma unroll
    for (int k = 0; k < 6; ++k) { hp[k] = 0ull; h1f[k] = 0.0f; }

    // producer-only: x stream + one-step-ahead x-projection
    const float2* xp = reinterpret_cast<const float2*>(x + (size_t)bc * (size_t)T * 6);
    ull xa01 = 0, xa23 = 0;
    if (producer) {
        float2 v0 = xp[0], v1 = xp[1], v2 = xp[2];
        float xin[6] = {v0.x, v0.y, v1.x, v1.y, v2.x, v2.y};
        xa01 = bzp01; xa23 = bzp23;
#pragma unroll
        for (int d = 0; d < 6; ++d) {
            ull xv = dup2(xin[d]);
            xa01 = ffma2(wip01[d], xv, xa01);
            xa23 = ffma2(wip23[d], xv, xa23);
        }
        asm volatile("prefetch.global.L2 [%0];" :: "l"(xp + 3 * 32));
    }

    const int NC = (T + CHUNK - 1) / CHUNK;

    for (int c = 0; c <= NC; ++c) {
        if (producer && c < NC) {
            // ---- produce chunk c: layer0 steps [c*CHUNK, c*CHUNK+steps) ----
            int t0 = c * CHUNK;
            int steps = (T - t0 < CHUNK) ? (T - t0) : CHUNK;
            float (*buf)[6] = h0buf[c & 1][0];   // [step][elem][unit] flattened below
            for (int kk = 0; kk < steps; ++kk) {
                int t = t0 + kk;
                // recurrent dots (x-projection precomputed last iteration)
                ull a01 = xa01, a23 = xa23;
#pragma unroll
                for (int d = 0; d < 6; ++d) {
                    a01 = ffma2(whp01[d], hp[d], a01);
                    a23 = ffma2(whp23[d], hp[d], a23);
                }
                // next x-projection (t+1) — independent, hides under tanh/shfl
                {
                    int tn = (t + 1 < T) ? (t + 1) : t;
                    float2 v0 = xp[3 * tn], v1 = xp[3 * tn + 1], v2 = xp[3 * tn + 2];
                    float xin[6] = {v0.x, v0.y, v1.x, v1.y, v2.x, v2.y};
                    xa01 = bzp01; xa23 = bzp23;
#pragma unroll
                    for (int d = 0; d < 6; ++d) {
                        ull xv = dup2(xin[d]);
                        xa01 = ffma2(wip01[d], xv, xa01);
                        xa23 = ffma2(wip23[d], xv, xa23);
                    }
                }
                if (t + 32 < T)
                    asm volatile("prefetch.global.L2 [%0];" :: "l"(xp + 3 * (t + 32)));

                float nh;
                gates_update(a01, a23, cst, nh);
                if (lactive) h0buf[c & 1][kk][eb][j] = nh;   // hand off own value
#pragma unroll
                for (int k = 0; k < 6; ++k) hp[k] = dup2(__shfl_sync(FULLMASK, nh, base + k));
            }
            (void)buf;
        }
        if (!producer && c > 0) {
            // ---- consume chunk c-1: layer1 steps [(c-1)*CHUNK, ...) ----
            int t0 = (c - 1) * CHUNK;
            int steps = (T - t0 < CHUNK) ? (T - t0) : CHUNK;
            int bi = (c - 1) & 1;
            for (int kk = 0; kk < steps; ++kk) {
                // input = h0 from smem (available whole chunk ahead of use)
                ull b01 = bzp01, b23 = bzp23;
#pragma unroll
                for (int d = 0; d < 6; ++d) {
                    ull xv = dup2(h0buf[bi][kk][lactive ? eb : 0][d]);
                    b01 = ffma2(wip01[d], xv, b01);
                    b23 = ffma2(wip23[d], xv, b23);
                }
                // own-layer recurrent dots
#pragma unroll
                for (int d = 0; d < 6; ++d) {
                    b01 = ffma2(whp01[d], hp[d], b01);
                    b23 = ffma2(whp23[d], hp[d], b23);
                }
                float nh;
                gates_update(b01, b23, cst, nh);
#pragma unroll
                for (int k = 0; k < 6; ++k) {
                    float hv = __shfl_sync(FULLMASK, nh, base + k);
                    hp[k]  = dup2(hv);
                    h1f[k] = hv;
                }
            }
        }
        __syncthreads();
    }

    // ---- softmax over 6 units (consumer warps own h1) ----
    if (!producer && valid) {
        float m = h1f[0];
#pragma unroll
        for (int k = 1; k < 6; ++k) m = fmaxf(m, h1f[k]);
        float s = 0.0f;
#pragma unroll
        for (int k = 0; k < 6; ++k) s += ex2f(1.4426950408889634f * (h1f[k] - m));
        float e = ex2f(1.4426950408889634f * (h1f[j] - m));
        out[b * 6 + j] = e * rcpf(s);
    }
}

extern "C" void kernel_launch(void* const* d_in, const int* in_sizes, int n_in,
                              void* d_out, int out_size) {
    const float* x    = (const float*)d_in[0];
    const float* Wih0 = (const float*)d_in[1];
    const float* Whh0 = (const float*)d_in[2];
    const float* bih0 = (const float*)d_in[3];
    const float* bhh0 = (const float*)d_in[4];
    const float* Wih1 = (const float*)d_in[5];
    const float* Whh1 = (const float*)d_in[6];
    const float* bih1 = (const float*)d_in[7];
    const float* bhh1 = (const float*)d_in[8];
    float* out = (float*)d_out;

    int B = out_size / 6;
    int T = (int)((long long)in_sizes[0] / ((long long)B * 6));

    int blocks = (B + 9) / 10;   // 10 batch elements per block
    stacked_lstm_kernel<<<blocks, 128>>>(x, Wih0, Whh0, bih0, bhh0,
                                         Wih1, Whh1, bih1, bhh1, out, B, T);
}